// round 10
// baseline (speedup 1.0000x reference)
#include <cuda_runtime.h>
#include <cstdint>

// ---- feature gate: tcgen05 only exists in sm_10xa / sm_10xf compilation passes ----
#if defined(__CUDA_ARCH__)
#  if defined(__CUDA_ARCH_FEAT_SM103_ALL) || defined(__CUDA_ARCH_FEAT_SM100_ALL) || \
      (defined(__CUDA_ARCH_FAMILY_SPECIFIC__) && (__CUDA_ARCH_FAMILY_SPECIFIC__ == 1000 || __CUDA_ARCH_FAMILY_SPECIFIC__ == 1030))
#    define HAS_TC 1
#  else
#    define HAS_TC 0
#  endif
#else
#  define HAS_TC 0
#endif

#define QLEN 2048
#define KLEN 2048
#define DDIM 128
#define BR   128
#define BC   64
#define NTILES (KLEN / BC)
#define NTHREADS 448
#define QSCALE (0.08838834764831845f * 1.4426950408889634f)

// ---- smem layout (offsets from 1024-aligned base) ----
#define SM_TMEMPTR 0
#define SM_QBAR    8
#define SM_TFULL0  16
#define SM_TFULL1  24
#define SM_SBAR0   32
#define SM_SBAR1   40
#define SM_PF0     48
#define SM_PF1     56
#define SM_DONE0   64
#define SM_DONE1   72
#define SM_OBAR    80
#define SM_Q    1024
#define SM_KV0  (SM_Q   + 65536)   // K (32KB, reused as P after MMA1) + V^T (32KB)
#define SM_KV1  (SM_KV0 + 65536)
#define SM_PART (SM_KV1 + 65536)
#define SMEM_BYTES (SM_PART + 1024 + 1024)

// tf32 idesc: dtype=f32(1)<<4 | atype=tf32(2)<<7 | btype=tf32(2)<<10 | (N/8)<<17 | (M/16)<<24
#define IDESC_S 0x8100910u   // M=128, N=64  (verified)
#define IDESC_O 0x8200910u   // M=128, N=128 (verified)

#define DESC_BASE_SW128 ((2ull<<61) | (1ull<<46) | (64ull<<32) | (1ull<<16))

__device__ __forceinline__ uint32_t swz(uint32_t off) { return off ^ ((off >> 3) & 0x70); }

__device__ __forceinline__ uint32_t cvt_tf32(float x) {
    uint32_t r; asm("cvt.rna.tf32.f32 %0, %1;" : "=r"(r) : "f"(x)); return r;
}
__device__ __forceinline__ float ex2f(float x) {
    float r; asm("ex2.approx.f32 %0, %1;" : "=f"(r) : "f"(x)); return r;
}
__device__ __forceinline__ uint32_t smem_u32(const void* p) {
    uint32_t a;
    asm("{ .reg .u64 t; cvta.to.shared.u64 t, %1; cvt.u32.u64 %0, t; }" : "=r"(a) : "l"(p));
    return a;
}

#define MBAR_INIT(a, n) asm volatile("mbarrier.init.shared.b64 [%0], %1;" :: "r"(a), "r"(n) : "memory")
#define MBAR_ARRIVE(a)  asm volatile("mbarrier.arrive.shared.b64 _, [%0];" :: "r"(a) : "memory")
#define MBAR_WAIT(a, ph) do {                                                         \
    uint32_t _m = (a), _p = (ph), _d;                                                 \
    asm volatile("{ .reg .pred p; mbarrier.try_wait.parity.acquire.cta.shared::cta.b64 p, [%1], %2; selp.b32 %0,1,0,p; }" \
        : "=r"(_d) : "r"(_m), "r"(_p) : "memory");                                    \
    if (!_d) {                                                                        \
        asm volatile("{ .reg .pred P1; WL%=: mbarrier.try_wait.parity.acquire.cta.shared::cta.b64 P1, [%0], %1, 0x989680; @P1 bra.uni WD%=; bra.uni WL%=; WD%=: }" \
            :: "r"(_m), "r"(_p) : "memory");                                          \
    }                                                                                 \
} while (0)

#if HAS_TC
#define FENCE_ASYNC()   asm volatile("fence.proxy.async.shared::cta;" ::: "memory")
#define TC_FENCE_BEF()  asm volatile("tcgen05.fence::before_thread_sync;" ::: "memory")
#define TC_FENCE_AFT()  asm volatile("tcgen05.fence::after_thread_sync;" ::: "memory")
#define TC_WAIT_LD()    asm volatile("tcgen05.wait::ld.sync.aligned;" ::: "memory")
#define TC_ALLOC(sa, n) asm volatile("tcgen05.alloc.cta_group::1.sync.aligned.shared::cta.b32 [%0], %1;" :: "r"(sa), "r"(n) : "memory")
#define TC_RELINQ()     asm volatile("tcgen05.relinquish_alloc_permit.cta_group::1.sync.aligned;")
#define TC_DEALLOC(t,n) asm volatile("tcgen05.dealloc.cta_group::1.sync.aligned.b32 %0, %1;" :: "r"(t), "r"(n))
#define TC_COMMIT(mb)   asm volatile("tcgen05.commit.cta_group::1.mbarrier::arrive::one.shared::cluster.b64 [%0];" :: "r"(mb) : "memory")

__device__ __forceinline__ uint32_t elect_one() {
    uint32_t p;
    asm volatile("{ .reg .pred p; elect.sync _|p, 0xFFFFFFFF; selp.b32 %0, 1, 0, p; }" : "=r"(p));
    return p;
}

#define LDTM32(r, ta) \
    asm volatile("tcgen05.ld.sync.aligned.32x32b.x32.b32 " \
        "{%0,%1,%2,%3,%4,%5,%6,%7,%8,%9,%10,%11,%12,%13,%14,%15," \
        "%16,%17,%18,%19,%20,%21,%22,%23,%24,%25,%26,%27,%28,%29,%30,%31}, [%32];" \
        : "=r"((r)[0]),"=r"((r)[1]),"=r"((r)[2]),"=r"((r)[3]),"=r"((r)[4]),"=r"((r)[5]),"=r"((r)[6]),"=r"((r)[7]), \
          "=r"((r)[8]),"=r"((r)[9]),"=r"((r)[10]),"=r"((r)[11]),"=r"((r)[12]),"=r"((r)[13]),"=r"((r)[14]),"=r"((r)[15]), \
          "=r"((r)[16]),"=r"((r)[17]),"=r"((r)[18]),"=r"((r)[19]),"=r"((r)[20]),"=r"((r)[21]),"=r"((r)[22]),"=r"((r)[23]), \
          "=r"((r)[24]),"=r"((r)[25]),"=r"((r)[26]),"=r"((r)[27]),"=r"((r)[28]),"=r"((r)[29]),"=r"((r)[30]),"=r"((r)[31]) \
        : "r"(ta))

// SS form: A desc, B desc
__device__ __forceinline__ void mma_ss_tf32(uint32_t d, uint64_t ad, uint64_t bd, uint32_t idesc, uint32_t en) {
    asm volatile("{ .reg .pred p; setp.ne.u32 p, %5, 0;"
        "tcgen05.mma.cta_group::1.kind::tf32 [%0], %1, %2, %3, {%4,%4,%4,%4}, p; }"
        :: "r"(d), "l"(ad), "l"(bd), "r"(idesc), "r"(0u), "r"(en) : "memory");
}
#endif  // HAS_TC

__global__ __launch_bounds__(NTHREADS, 1)
void fa_tc_kernel(const float* __restrict__ Q, const float* __restrict__ K,
                  const float* __restrict__ V, float* __restrict__ O) {
#if HAS_TC
    extern __shared__ char smem_raw[];
    uint32_t sb = (smem_u32(smem_raw) + 1023u) & ~1023u;
    char* smem = smem_raw + (sb - smem_u32(smem_raw));

    const int tid  = threadIdx.x;
    const int warp = tid >> 5;
    const int b    = blockIdx.y;
    const int qt   = blockIdx.x;

    const float* Qg = Q + ((size_t)b * QLEN + (size_t)qt * BR) * DDIM;
    const float* Kg = K + (size_t)b * KLEN * DDIM;
    const float* Vg = V + (size_t)b * KLEN * DDIM;
    float*       Og = O + ((size_t)b * QLEN + (size_t)qt * BR) * DDIM;

    if (tid == 0) {
        MBAR_INIT(sb + SM_QBAR,   4);
        MBAR_INIT(sb + SM_TFULL0, 4);
        MBAR_INIT(sb + SM_TFULL1, 4);
        MBAR_INIT(sb + SM_SBAR0,  1);
        MBAR_INIT(sb + SM_SBAR1,  1);
        MBAR_INIT(sb + SM_PF0,    4);
        MBAR_INIT(sb + SM_PF1,    4);
        MBAR_INIT(sb + SM_DONE0,  1);
        MBAR_INIT(sb + SM_DONE1,  1);
        MBAR_INIT(sb + SM_OBAR,   1);
    }
    if (warp == 12) {
        TC_ALLOC(sb + SM_TMEMPTR, 256);
        TC_RELINQ();
    }
    __syncthreads();                                      // sync #1

    uint32_t tmem_base;
    asm volatile("ld.shared.b32 %0, [%1];" : "=r"(tmem_base) : "r"(sb + SM_TMEMPTR));
    const uint32_t TM_S[2] = { tmem_base, tmem_base + 64 };
    const uint32_t TM_O    = tmem_base + 128;             // 128 cols fp32

    const uint32_t kvoffs[2] = { SM_KV0, SM_KV1 };
    float* PART = reinterpret_cast<float*>(smem + SM_PART);

    if (tid < 256) {
        // ========== softmax warpgroups: wg0 even tiles (S0), wg1 odd (S1) ==========
        const int wg     = tid >> 7;
        const int wg_tid = tid & 127;
        const uint32_t tms  = TM_S[wg];
        const uint32_t sbar = sb + (wg ? SM_SBAR1 : SM_SBAR0);
        const uint32_t pfb  = sb + (wg ? SM_PF1   : SM_PF0);
        const uint32_t dnb  = sb + (wg ? SM_DONE1 : SM_DONE0);
        char* pbase = smem + kvoffs[wg];                  // P overwrites K region of own buffer
        const uint32_t prow = (uint32_t)wg_tid * 128;

        float acc0 = 0.f, acc1 = 0.f;
        for (int u = 0; u < NTILES / 2; u++) {            // tile t = 2u + wg
            MBAR_WAIT(sbar, (uint32_t)(u & 1));
            TC_FENCE_AFT();
            uint32_t ra[32], rb2[32];
            LDTM32(ra, tms);
            LDTM32(rb2, tms + 32);
            TC_WAIT_LD();
            #pragma unroll
            for (int i = 0; i < 32; i++) {
                float e0 = ex2f(__uint_as_float(ra[i]));
                float e1 = ex2f(__uint_as_float(rb2[i]));
                acc0 += e0;
                acc1 += e1;
                ra[i]  = cvt_tf32(e0);
                rb2[i] = cvt_tf32(e1);
            }
            if (u >= 1) {                                 // P region reuse: MMA2(prev own tile) done
                MBAR_WAIT(dnb, (uint32_t)((u - 1) & 1));
            }
            // STS P: row wg_tid, 64 tf32 cols; blocked SW128 K-major (2 blocks of 128x128B)
            #pragma unroll
            for (int f = 0; f < 8; f++) {
                uint4 v0 = make_uint4(ra[f*4], ra[f*4+1], ra[f*4+2], ra[f*4+3]);
                uint4 v1 = make_uint4(rb2[f*4], rb2[f*4+1], rb2[f*4+2], rb2[f*4+3]);
                *reinterpret_cast<uint4*>(pbase + swz(prow + f * 16))         = v0;
                *reinterpret_cast<uint4*>(pbase + swz(16384u + prow + f * 16)) = v1;
            }
            FENCE_ASYNC();
            __syncwarp();
            if (elect_one()) MBAR_ARRIVE(pfb);
        }
        // ---- epilogue ----
        PART[wg * 128 + wg_tid] = acc0 + acc1;
        __syncthreads();                                  // sync #2 (all threads)
        float inv = 1.f / (PART[wg_tid] + PART[128 + wg_tid]);
        MBAR_WAIT(sb + SM_OBAR, 0u);                      // all MMA2 complete
        TC_FENCE_AFT();
        #pragma unroll
        for (int j = 0; j < 2; j++) {
            uint32_t ro[32];
            LDTM32(ro, TM_O + wg * 64 + j * 32);
            TC_WAIT_LD();
            const int cb = wg * 64 + j * 32;
            #pragma unroll
            for (int g = 0; g < 8; g++) {
                float4 f;
                f.x = __uint_as_float(ro[g * 4 + 0]) * inv;
                f.y = __uint_as_float(ro[g * 4 + 1]) * inv;
                f.z = __uint_as_float(ro[g * 4 + 2]) * inv;
                f.w = __uint_as_float(ro[g * 4 + 3]) * inv;
                *reinterpret_cast<float4*>(Og + (size_t)wg_tid * DDIM + cb + g * 4) = f;
            }
        }
    } else if (tid < 384) {
        // ========== loader warps: Q (swizzled, once) + 2-deep KV pipeline ==========
        const int lt = tid - 256;
        #pragma unroll
        for (int i = 0; i < 32; i++) {
            int idx = lt + i * 128;
            int r = idx >> 5, c4 = idx & 31;
            float4 v = reinterpret_cast<const float4*>(Qg)[idx];
            uint4 u;
            u.x = cvt_tf32(v.x * QSCALE); u.y = cvt_tf32(v.y * QSCALE);
            u.z = cvt_tf32(v.z * QSCALE); u.w = cvt_tf32(v.w * QSCALE);
            uint32_t off = (uint32_t)((c4 >> 3) * 16384 + r * 128 + (c4 & 7) * 16);
            *reinterpret_cast<uint4*>(smem + SM_Q + swz(off)) = u;
        }
        FENCE_ASYNC();
        __syncwarp();
        if (elect_one()) MBAR_ARRIVE(sb + SM_QBAR);

        const int d_lo = lt & 7, kv_lo = (lt >> 3) & 3, wl = lt >> 5;
        for (int t = 0; t < NTILES; t++) {
            const int buf = t & 1;
            if (t >= 2) {   // K/P/V region reuse: MMA2(t-2) complete
                MBAR_WAIT(sb + (buf ? SM_DONE1 : SM_DONE0), (uint32_t)(((t >> 1) - 1) & 1));
            }
            const uint32_t koff = kvoffs[buf];
            const uint32_t voff = koff + 32768;
            const float* Kt = Kg + (size_t)t * BC * DDIM;
            const float* Vt = Vg + (size_t)t * BC * DDIM;
            #pragma unroll
            for (int i = 0; i < 16; i++) {
                int idx = lt + i * 128;
                int r = idx >> 5, c4 = idx & 31;
                float4 v = reinterpret_cast<const float4*>(Kt)[idx];
                uint4 u;
                u.x = cvt_tf32(v.x); u.y = cvt_tf32(v.y);
                u.z = cvt_tf32(v.z); u.w = cvt_tf32(v.w);
                uint32_t off = (uint32_t)((c4 >> 3) * 8192 + r * 128 + (c4 & 7) * 16);
                *reinterpret_cast<uint4*>(smem + koff + swz(off)) = u;
            }
            // V transpose: gmem [kv][d] -> smem V^T [128 d rows][64 kv cols], conflict-free
            #pragma unroll
            for (int i = 0; i < 64; i++) {
                int kv = ((i & 15) << 2) | kv_lo;
                int d  = d_lo + 8 * wl + 32 * (i >> 4);
                uint32_t val = cvt_tf32(__ldg(Vt + (size_t)kv * DDIM + d));
                uint32_t off = (uint32_t)((kv >> 5) * 16384 + d * 128 + (kv & 31) * 4);
                *reinterpret_cast<uint32_t*>(smem + voff + swz(off)) = val;
            }
            FENCE_ASYNC();
            __syncwarp();
            if (elect_one()) MBAR_ARRIVE(sb + (buf ? SM_TFULL1 : SM_TFULL0));
        }
        __syncthreads();                                  // sync #2
    } else if (warp == 12) {
        // ========== MMA1 issuer (SS): S[t&1] = Q(smem) x K[t&1] ==========
        const uint64_t qdesc = DESC_BASE_SW128 | (((uint64_t)(sb + SM_Q) >> 4) & 0x3FFF);
        uint64_t kdesc[2];
        #pragma unroll
        for (int i = 0; i < 2; i++)
            kdesc[i] = DESC_BASE_SW128 | (((uint64_t)(sb + kvoffs[i]) >> 4) & 0x3FFF);

        MBAR_WAIT(sb + SM_QBAR, 0u);
        TC_FENCE_AFT();
        for (int t = 0; t < NTILES; t++) {
            const int bu = t & 1, u = t >> 1;
            MBAR_WAIT(sb + (bu ? SM_TFULL1 : SM_TFULL0), (uint32_t)(u & 1));
            if (t >= 2) MBAR_WAIT(sb + (bu ? SM_PF1 : SM_PF0), (uint32_t)((u - 1) & 1)); // S reuse: LDTM(t-2) done
            TC_FENCE_AFT();
            if (elect_one()) {
                #pragma unroll
                for (int kk = 0; kk < 16; kk++) {
                    uint64_t dq = (uint64_t)(((kk >> 2) << 10) + ((kk & 3) << 1));
                    uint64_t dk = (uint64_t)(((kk >> 2) << 9)  + ((kk & 3) << 1));
                    mma_ss_tf32(TM_S[bu], qdesc + dq, kdesc[bu] + dk, IDESC_S, (uint32_t)(kk > 0));
                }
                TC_COMMIT(sb + (bu ? SM_SBAR1 : SM_SBAR0));
            }
        }
        __syncthreads();                                  // sync #2
    } else {
        // ========== MMA2 issuer (SS, warp 13): O += P(smem) x V^T(smem) ==========
        uint64_t pdesc[2], vdesc[2];
        #pragma unroll
        for (int i = 0; i < 2; i++) {
            pdesc[i] = DESC_BASE_SW128 | (((uint64_t)(sb + kvoffs[i]) >> 4) & 0x3FFF);
            vdesc[i] = DESC_BASE_SW128 | (((uint64_t)(sb + kvoffs[i] + 32768) >> 4) & 0x3FFF);
        }
        for (int t = 0; t < NTILES; t++) {
            const int bp = t & 1;
            MBAR_WAIT(sb + (bp ? SM_PF1 : SM_PF0), (uint32_t)((t >> 1) & 1));
            TC_FENCE_AFT();
            if (elect_one()) {
                #pragma unroll
                for (int kk = 0; kk < 8; kk++) {
                    // P: 128x64 K-major, 2 blocks (16KB=1024 units); V^T: same geometry
                    uint64_t da = (uint64_t)(((kk >> 2) << 10) + ((kk & 3) << 1));
                    mma_ss_tf32(TM_O, pdesc[bp] + da, vdesc[bp] + da, IDESC_O,
                                (uint32_t)((t > 0) || (kk > 0)));
                }
                TC_COMMIT(sb + (bp ? SM_DONE1 : SM_DONE0));
            }
        }
        if (elect_one()) TC_COMMIT(sb + SM_OBAR);         // after all MMA2 complete
        __syncthreads();                                  // sync #2
    }

    __syncthreads();                                      // sync #3
    if (warp == 12) TC_DEALLOC(tmem_base, 256);
#endif  // HAS_TC
}

extern "C" void kernel_launch(void* const* d_in, const int* in_sizes, int n_in,
                              void* d_out, int out_size) {
    const float* q = (const float*)d_in[0];
    const float* k = (const float*)d_in[1];
    const float* v = (const float*)d_in[2];
    float* o = (float*)d_out;

    cudaFuncSetAttribute(fa_tc_kernel, cudaFuncAttributeMaxDynamicSharedMemorySize, SMEM_BYTES);
    dim3 grid(QLEN / BR, 16);
    fa_tc_kernel<<<grid, NTHREADS, SMEM_BYTES>>>(q, k, v, o);
}

// round 11
// speedup vs baseline: 1.6905x; 1.6905x over previous
#include <cuda_runtime.h>
#include <cstdint>

// ---- feature gate: tcgen05 only exists in sm_10xa / sm_10xf compilation passes ----
#if defined(__CUDA_ARCH__)
#  if defined(__CUDA_ARCH_FEAT_SM103_ALL) || defined(__CUDA_ARCH_FEAT_SM100_ALL) || \
      (defined(__CUDA_ARCH_FAMILY_SPECIFIC__) && (__CUDA_ARCH_FAMILY_SPECIFIC__ == 1000 || __CUDA_ARCH_FAMILY_SPECIFIC__ == 1030))
#    define HAS_TC 1
#  else
#    define HAS_TC 0
#  endif
#else
#  define HAS_TC 0
#endif

#define QLEN 2048
#define KLEN 2048
#define DDIM 128
#define BR   128
#define BC   64
#define NTILES (KLEN / BC)
#define NTHREADS 448
#define QSCALE (0.08838834764831845f * 1.4426950408889634f)

// ---- smem layout (offsets from 1024-aligned base) ----
#define SM_TMEMPTR 0
#define SM_QBAR    8
#define SM_TFULL0  16
#define SM_TFULL1  24
#define SM_SBAR0   32
#define SM_SBAR1   40
#define SM_PF0     48
#define SM_PF1     56
#define SM_DONE0   64
#define SM_DONE1   72
#define SM_OBAR    80
#define SM_Q    1024                       // 128x128 fp16 = 32KB
#define SM_KV0  (SM_Q   + 32768)           // K fp16 16KB + V^T fp16 16KB
#define SM_KV1  (SM_KV0 + 32768)
#define SM_PART (SM_KV1 + 32768)
#define SMEM_BYTES (SM_PART + 1024 + 1024) // ~100KB -> 2 CTAs/SM

// f16 idesc: dtype=f32(1)<<4 | atype=f16(0)<<7 | btype=f16(0)<<10 | (N/8)<<17 | (M/16)<<24
#define IDESC_S 0x8100010u   // M=128, N=64
#define IDESC_O 0x8200010u   // M=128, N=128

#define DESC_BASE_SW128 ((2ull<<61) | (1ull<<46) | (64ull<<32) | (1ull<<16))

__device__ __forceinline__ uint32_t swz(uint32_t off) { return off ^ ((off >> 3) & 0x70); }

__device__ __forceinline__ uint32_t pack_h2(float lo, float hi) {
    uint32_t r; asm("cvt.rn.f16x2.f32 %0, %1, %2;" : "=r"(r) : "f"(hi), "f"(lo)); return r;
}
__device__ __forceinline__ float ex2f(float x) {
    float r; asm("ex2.approx.f32 %0, %1;" : "=f"(r) : "f"(x)); return r;
}
__device__ __forceinline__ uint32_t smem_u32(const void* p) {
    uint32_t a;
    asm("{ .reg .u64 t; cvta.to.shared.u64 t, %1; cvt.u32.u64 %0, t; }" : "=r"(a) : "l"(p));
    return a;
}

#define MBAR_INIT(a, n) asm volatile("mbarrier.init.shared.b64 [%0], %1;" :: "r"(a), "r"(n) : "memory")
#define MBAR_ARRIVE(a)  asm volatile("mbarrier.arrive.shared.b64 _, [%0];" :: "r"(a) : "memory")
#define MBAR_WAIT(a, ph) do {                                                         \
    uint32_t _m = (a), _p = (ph), _d;                                                 \
    asm volatile("{ .reg .pred p; mbarrier.try_wait.parity.acquire.cta.shared::cta.b64 p, [%1], %2; selp.b32 %0,1,0,p; }" \
        : "=r"(_d) : "r"(_m), "r"(_p) : "memory");                                    \
    if (!_d) {                                                                        \
        asm volatile("{ .reg .pred P1; WL%=: mbarrier.try_wait.parity.acquire.cta.shared::cta.b64 P1, [%0], %1, 0x989680; @P1 bra.uni WD%=; bra.uni WL%=; WD%=: }" \
            :: "r"(_m), "r"(_p) : "memory");                                          \
    }                                                                                 \
} while (0)

#if HAS_TC
#define FENCE_ASYNC()   asm volatile("fence.proxy.async.shared::cta;" ::: "memory")
#define TC_FENCE_BEF()  asm volatile("tcgen05.fence::before_thread_sync;" ::: "memory")
#define TC_FENCE_AFT()  asm volatile("tcgen05.fence::after_thread_sync;" ::: "memory")
#define TC_WAIT_LD()    asm volatile("tcgen05.wait::ld.sync.aligned;" ::: "memory")
#define TC_WAIT_ST()    asm volatile("tcgen05.wait::st.sync.aligned;" ::: "memory")
#define TC_ALLOC(sa, n) asm volatile("tcgen05.alloc.cta_group::1.sync.aligned.shared::cta.b32 [%0], %1;" :: "r"(sa), "r"(n) : "memory")
#define TC_RELINQ()     asm volatile("tcgen05.relinquish_alloc_permit.cta_group::1.sync.aligned;")
#define TC_DEALLOC(t,n) asm volatile("tcgen05.dealloc.cta_group::1.sync.aligned.b32 %0, %1;" :: "r"(t), "r"(n))
#define TC_COMMIT(mb)   asm volatile("tcgen05.commit.cta_group::1.mbarrier::arrive::one.shared::cluster.b64 [%0];" :: "r"(mb) : "memory")

__device__ __forceinline__ uint32_t elect_one() {
    uint32_t p;
    asm volatile("{ .reg .pred p; elect.sync _|p, 0xFFFFFFFF; selp.b32 %0, 1, 0, p; }" : "=r"(p));
    return p;
}

#define LDTM32(r, ta) \
    asm volatile("tcgen05.ld.sync.aligned.32x32b.x32.b32 " \
        "{%0,%1,%2,%3,%4,%5,%6,%7,%8,%9,%10,%11,%12,%13,%14,%15," \
        "%16,%17,%18,%19,%20,%21,%22,%23,%24,%25,%26,%27,%28,%29,%30,%31}, [%32];" \
        : "=r"((r)[0]),"=r"((r)[1]),"=r"((r)[2]),"=r"((r)[3]),"=r"((r)[4]),"=r"((r)[5]),"=r"((r)[6]),"=r"((r)[7]), \
          "=r"((r)[8]),"=r"((r)[9]),"=r"((r)[10]),"=r"((r)[11]),"=r"((r)[12]),"=r"((r)[13]),"=r"((r)[14]),"=r"((r)[15]), \
          "=r"((r)[16]),"=r"((r)[17]),"=r"((r)[18]),"=r"((r)[19]),"=r"((r)[20]),"=r"((r)[21]),"=r"((r)[22]),"=r"((r)[23]), \
          "=r"((r)[24]),"=r"((r)[25]),"=r"((r)[26]),"=r"((r)[27]),"=r"((r)[28]),"=r"((r)[29]),"=r"((r)[30]),"=r"((r)[31]) \
        : "r"(ta))

#define STTM32(ta, r) \
    asm volatile("tcgen05.st.sync.aligned.32x32b.x32.b32 [%0], " \
        "{%1,%2,%3,%4,%5,%6,%7,%8,%9,%10,%11,%12,%13,%14,%15,%16," \
        "%17,%18,%19,%20,%21,%22,%23,%24,%25,%26,%27,%28,%29,%30,%31,%32};" \
        :: "r"(ta), \
          "r"((r)[0]),"r"((r)[1]),"r"((r)[2]),"r"((r)[3]),"r"((r)[4]),"r"((r)[5]),"r"((r)[6]),"r"((r)[7]), \
          "r"((r)[8]),"r"((r)[9]),"r"((r)[10]),"r"((r)[11]),"r"((r)[12]),"r"((r)[13]),"r"((r)[14]),"r"((r)[15]), \
          "r"((r)[16]),"r"((r)[17]),"r"((r)[18]),"r"((r)[19]),"r"((r)[20]),"r"((r)[21]),"r"((r)[22]),"r"((r)[23]), \
          "r"((r)[24]),"r"((r)[25]),"r"((r)[26]),"r"((r)[27]),"r"((r)[28]),"r"((r)[29]),"r"((r)[30]),"r"((r)[31]) \
        : "memory")

// SS form: A desc, B desc
__device__ __forceinline__ void mma_ss_f16(uint32_t d, uint64_t ad, uint64_t bd, uint32_t idesc, uint32_t en) {
    asm volatile("{ .reg .pred p; setp.ne.u32 p, %5, 0;"
        "tcgen05.mma.cta_group::1.kind::f16 [%0], %1, %2, %3, {%4,%4,%4,%4}, p; }"
        :: "r"(d), "l"(ad), "l"(bd), "r"(idesc), "r"(0u), "r"(en) : "memory");
}
// TS form: A in TMEM (fp16x2 cols), B desc
__device__ __forceinline__ void mma_ts_f16(uint32_t d, uint32_t at, uint64_t bd, uint32_t idesc, uint32_t en) {
    asm volatile("{ .reg .pred p; setp.ne.u32 p, %5, 0;"
        "tcgen05.mma.cta_group::1.kind::f16 [%0], [%1], %2, %3, {%4,%4,%4,%4}, p; }"
        :: "r"(d), "r"(at), "l"(bd), "r"(idesc), "r"(0u), "r"(en) : "memory");
}
#endif  // HAS_TC

__global__ __launch_bounds__(NTHREADS, 2)
void fa_tc_kernel(const float* __restrict__ Q, const float* __restrict__ K,
                  const float* __restrict__ V, float* __restrict__ O) {
#if HAS_TC
    extern __shared__ char smem_raw[];
    uint32_t sb = (smem_u32(smem_raw) + 1023u) & ~1023u;
    char* smem = smem_raw + (sb - smem_u32(smem_raw));

    const int tid  = threadIdx.x;
    const int warp = tid >> 5;
    const int b    = blockIdx.y;
    const int qt   = blockIdx.x;

    const float* Qg = Q + ((size_t)b * QLEN + (size_t)qt * BR) * DDIM;
    const float* Kg = K + (size_t)b * KLEN * DDIM;
    const float* Vg = V + (size_t)b * KLEN * DDIM;
    float*       Og = O + ((size_t)b * QLEN + (size_t)qt * BR) * DDIM;

    if (tid == 0) {
        MBAR_INIT(sb + SM_QBAR,   4);
        MBAR_INIT(sb + SM_TFULL0, 4);
        MBAR_INIT(sb + SM_TFULL1, 4);
        MBAR_INIT(sb + SM_SBAR0,  1);
        MBAR_INIT(sb + SM_SBAR1,  1);
        MBAR_INIT(sb + SM_PF0,    4);
        MBAR_INIT(sb + SM_PF1,    4);
        MBAR_INIT(sb + SM_DONE0,  1);
        MBAR_INIT(sb + SM_DONE1,  1);
        MBAR_INIT(sb + SM_OBAR,   1);
    }
    if (warp == 12) {
        TC_ALLOC(sb + SM_TMEMPTR, 256);      // 256 cols/CTA -> two CTAs share 512
        TC_RELINQ();
    }
    __syncthreads();                                      // sync #1

    uint32_t tmem_base;
    asm volatile("ld.shared.b32 %0, [%1];" : "=r"(tmem_base) : "r"(sb + SM_TMEMPTR));
    const uint32_t TM_SP[2] = { tmem_base, tmem_base + 64 };  // S fp32 64 cols; P fp16x2 in cols 0-31
    const uint32_t TM_O     = tmem_base + 128;                 // 128 cols fp32

    const uint32_t kvoffs[2] = { SM_KV0, SM_KV1 };
    float* PART = reinterpret_cast<float*>(smem + SM_PART);

    if (tid < 256) {
        // ========== softmax warpgroups: wg0 even tiles (SP0), wg1 odd (SP1) ==========
        const int wg     = tid >> 7;
        const int wg_tid = tid & 127;
        const uint32_t woff = (uint32_t)(wg_tid >> 5) << 21;
        const uint32_t tmsp = TM_SP[wg];
        const uint32_t sbar = sb + (wg ? SM_SBAR1 : SM_SBAR0);
        const uint32_t pfb  = sb + (wg ? SM_PF1   : SM_PF0);

        float acc0 = 0.f, acc1 = 0.f;
        for (int u = 0; u < NTILES / 2; u++) {            // tile t = 2u + wg
            MBAR_WAIT(sbar, (uint32_t)(u & 1));
            TC_FENCE_AFT();
            uint32_t ra[32], rb2[32];
            LDTM32(ra, tmsp);
            LDTM32(rb2, tmsp + 32);
            TC_WAIT_LD();
            float ea[32], eb[32];
            #pragma unroll
            for (int i = 0; i < 32; i++) {
                ea[i] = ex2f(__uint_as_float(ra[i]));     // logits already in log2 domain
                eb[i] = ex2f(__uint_as_float(rb2[i]));
                acc0 += ea[i];
                acc1 += eb[i];
            }
            uint32_t p[32];
            #pragma unroll
            for (int j = 0; j < 16; j++) {
                p[j]      = pack_h2(ea[2 * j], ea[2 * j + 1]);   // kv pair (2j, 2j+1)
                p[16 + j] = pack_h2(eb[2 * j], eb[2 * j + 1]);   // kv pair (32+2j, 33+2j)
            }
            // P (fp16x2, 32 cols) overwrites S cols 0-31 in place.
            // Safe: SBAR(t) => MMA1(t) issued => DONE(t-2) observed => MMA2(t-2) done with these cols.
            STTM32(tmsp + woff, p);
            TC_WAIT_ST();
            TC_FENCE_BEF();
            __syncwarp();
            if (elect_one()) MBAR_ARRIVE(pfb);
        }
        // ---- epilogue ----
        PART[wg * 128 + wg_tid] = acc0 + acc1;
        __syncthreads();                                  // sync #2 (all threads)
        float inv = 1.f / (PART[wg_tid] + PART[128 + wg_tid]);
        MBAR_WAIT(sb + SM_OBAR, 0u);                      // all MMA2 complete
        TC_FENCE_AFT();
        #pragma unroll
        for (int j = 0; j < 2; j++) {
            uint32_t ro[32];
            LDTM32(ro, TM_O + wg * 64 + j * 32);
            TC_WAIT_LD();
            const int cb = wg * 64 + j * 32;
            #pragma unroll
            for (int g = 0; g < 8; g++) {
                float4 f;
                f.x = __uint_as_float(ro[g * 4 + 0]) * inv;
                f.y = __uint_as_float(ro[g * 4 + 1]) * inv;
                f.z = __uint_as_float(ro[g * 4 + 2]) * inv;
                f.w = __uint_as_float(ro[g * 4 + 3]) * inv;
                *reinterpret_cast<float4*>(Og + (size_t)wg_tid * DDIM + cb + g * 4) = f;
            }
        }
    } else if (tid < 384) {
        // ========== loader warps: Q fp16 (once) + 2-deep KV fp16 pipeline ==========
        const int lt = tid - 256;
        // Q: 128x128 fp32 -> fp16 scaled; blocked SW128 (2 blocks of 128 rows x 128B)
        #pragma unroll
        for (int i = 0; i < 32; i++) {
            int idx = lt + i * 128;                       // float4 index over 4096
            int r = idx >> 5, c4 = idx & 31;
            float4 v = reinterpret_cast<const float4*>(Qg)[idx];
            uint2 u;
            u.x = pack_h2(v.x * QSCALE, v.y * QSCALE);
            u.y = pack_h2(v.z * QSCALE, v.w * QSCALE);
            uint32_t off = (uint32_t)((c4 >> 4) * 16384 + r * 128 + (c4 & 15) * 8);
            *reinterpret_cast<uint2*>(smem + SM_Q + swz(off)) = u;
        }
        FENCE_ASYNC();
        __syncwarp();
        if (elect_one()) MBAR_ARRIVE(sb + SM_QBAR);

        const int d_lo = lt & 7, kv_lo = (lt >> 3) & 3, wl = lt >> 5;
        for (int t = 0; t < NTILES; t++) {
            const int buf = t & 1;
            if (t >= 2) {   // KV[buf] reuse: MMA2(t-2) complete (MMA1(t-2) completed even earlier)
                MBAR_WAIT(sb + (buf ? SM_DONE1 : SM_DONE0), (uint32_t)(((t >> 1) - 1) & 1));
            }
            const uint32_t koff = kvoffs[buf];
            const uint32_t voff = koff + 16384;
            const float* Kt = Kg + (size_t)t * BC * DDIM;
            const float* Vt = Vg + (size_t)t * BC * DDIM;
            // K: 64 rows x 128 d fp16, blocked SW128 (2 blocks of 64 rows x 128B)
            #pragma unroll
            for (int i = 0; i < 16; i++) {
                int idx = lt + i * 128;                   // float4 index over 2048
                int r = idx >> 5, c4 = idx & 31;
                float4 v = reinterpret_cast<const float4*>(Kt)[idx];
                uint2 u;
                u.x = pack_h2(v.x, v.y);
                u.y = pack_h2(v.z, v.w);
                uint32_t off = (uint32_t)((c4 >> 4) * 8192 + r * 128 + (c4 & 15) * 8);
                *reinterpret_cast<uint2*>(smem + koff + swz(off)) = u;
            }
            // V transpose: gmem [kv][d] -> smem V^T [128 d rows x 64 kv fp16 = 128B/row]
            // kv handled in pairs -> fp16x2 store; mapping is 32-bank conflict-free.
            #pragma unroll
            for (int i = 0; i < 32; i++) {
                int kv2 = ((i & 7) << 3) | (kv_lo << 1);
                int d   = d_lo + 8 * wl + 32 * (i >> 3);
                float v0 = __ldg(Vt + (size_t)kv2 * DDIM + d);
                float v1 = __ldg(Vt + (size_t)(kv2 + 1) * DDIM + d);
                uint32_t off = (uint32_t)(d * 128 + kv2 * 2);
                *reinterpret_cast<uint32_t*>(smem + voff + swz(off)) = pack_h2(v0, v1);
            }
            FENCE_ASYNC();
            __syncwarp();
            if (elect_one()) MBAR_ARRIVE(sb + (buf ? SM_TFULL1 : SM_TFULL0));
        }
        __syncthreads();                                  // sync #2
    } else if (warp == 12) {
        // ========== MMA1 issuer (SS f16): S[t&1] = Q(smem) x K[t&1] ==========
        const uint64_t qdesc = DESC_BASE_SW128 | (((uint64_t)(sb + SM_Q) >> 4) & 0x3FFF);
        uint64_t kdesc[2];
        #pragma unroll
        for (int i = 0; i < 2; i++)
            kdesc[i] = DESC_BASE_SW128 | (((uint64_t)(sb + kvoffs[i]) >> 4) & 0x3FFF);

        MBAR_WAIT(sb + SM_QBAR, 0u);
        TC_FENCE_AFT();
        for (int t = 0; t < NTILES; t++) {
            const int bu = t & 1, u = t >> 1;
            MBAR_WAIT(sb + (bu ? SM_TFULL1 : SM_TFULL0), (uint32_t)(u & 1));
            if (t >= 2) {   // S/P[bu] reuse: MMA2(t-2) done reading P cols
                MBAR_WAIT(sb + (bu ? SM_DONE1 : SM_DONE0), (uint32_t)((u - 1) & 1));
            }
            TC_FENCE_AFT();
            if (elect_one()) {
                #pragma unroll
                for (int kk = 0; kk < 8; kk++) {          // K=128, 16 per f16 MMA
                    uint64_t dq = (uint64_t)(((kk >> 2) << 10) + ((kk & 3) << 1));
                    uint64_t dk = (uint64_t)(((kk >> 2) << 9)  + ((kk & 3) << 1));
                    mma_ss_f16(TM_SP[bu], qdesc + dq, kdesc[bu] + dk, IDESC_S, (uint32_t)(kk > 0));
                }
                TC_COMMIT(sb + (bu ? SM_SBAR1 : SM_SBAR0));
            }
        }
        __syncthreads();                                  // sync #2
    } else {
        // ========== MMA2 issuer (TS f16, warp 13): O += P(tmem) x V^T(smem) ==========
        uint64_t vdesc[2];
        #pragma unroll
        for (int i = 0; i < 2; i++)
            vdesc[i] = DESC_BASE_SW128 | (((uint64_t)(sb + kvoffs[i] + 16384) >> 4) & 0x3FFF);

        for (int t = 0; t < NTILES; t++) {
            const int bp = t & 1;
            MBAR_WAIT(sb + (bp ? SM_PF1 : SM_PF0), (uint32_t)((t >> 1) & 1));
            TC_FENCE_AFT();
            if (elect_one()) {
                #pragma unroll
                for (int kk = 0; kk < 4; kk++) {          // Bc=64, 16 kv per f16 MMA
                    mma_ts_f16(TM_O, TM_SP[bp] + kk * 8, vdesc[bp] + (uint64_t)(kk * 2),
                               IDESC_O, (uint32_t)((t > 0) || (kk > 0)));
                }
                TC_COMMIT(sb + (bp ? SM_DONE1 : SM_DONE0));
            }
        }
        if (elect_one()) TC_COMMIT(sb + SM_OBAR);         // after all MMA2 complete
        __syncthreads();                                  // sync #2
    }

    __syncthreads();                                      // sync #3
    if (warp == 12) TC_DEALLOC(tmem_base, 256);
#endif  // HAS_TC
}

extern "C" void kernel_launch(void* const* d_in, const int* in_sizes, int n_in,
                              void* d_out, int out_size) {
    const float* q = (const float*)d_in[0];
    const float* k = (const float*)d_in[1];
    const float* v = (const float*)d_in[2];
    float* o = (float*)d_out;

    cudaFuncSetAttribute(fa_tc_kernel, cudaFuncAttributeMaxDynamicSharedMemorySize, SMEM_BYTES);
    dim3 grid(QLEN / BR, 16);
    fa_tc_kernel<<<grid, NTHREADS, SMEM_BYTES>>>(q, k, v, o);
}